// round 14
// baseline (speedup 1.0000x reference)
#include <cuda_runtime.h>
#include <cstdint>

// ---------------------------------------------------------------------------
// TT embedding:  VOC = 100^3,  EMB = 4*4*8 = 128,  RANK = 16
//   out[tok, n1*32+n2*8+n3] = sum_{r1,r2} core0[i1,n1,r1]*core1[r1,i2,n2,r2]*core2[r2,i3,n3]
// idx = i1*10000 + i2*100 + i3; idx==0 (PAD) -> zero row.
//
// Kernel 1 : G01[i12][row*16+r2] = sum_r1 core0*core1  (10.2MB, L2-resident)
//            + fused pack of core2 into C2Q (51KB), r2 = 4c+j.  No smem.
//            Each thread triggers programmatic launch completion right after
//            its last store (release semantics for the PDL pairing).
// Kernel 2 : warp/token, minimal-wavefront layout (R10/R12 frozen), launched
//            with PDL: index load + address math run BEFORE
//            cudaGridDependencySynchronize(), overlapping precompute's tail.
//   G: 2x contiguous LDG.128 (8 wf).  C: 8 instr, one 128B line each (8 wf),
//   address-permuted so reduce round 1 needs no selects.  2-round
//   reduce-scatter, 2x contiguous STG.64.  Launch bounds (256,6): regs ~40
//   (caps forcing 32 regs kill ptxas load batching -- verified R8, R11).
// ---------------------------------------------------------------------------

#define VOC_LL 1000000ULL

__device__ float g_G01[10000 * 256];
__device__ float g_C2Q[100 * 128];   // [i3][j][c][n3] = core2[4c+j][i3][n3]

// ---- packed fp32x2 helpers (sm_103a) --------------------------------------
__device__ __forceinline__ unsigned long long f32x2_fma(
    unsigned long long a, unsigned long long b, unsigned long long c)
{
    unsigned long long d;
    asm("fma.rn.f32x2 %0, %1, %2, %3;" : "=l"(d) : "l"(a), "l"(b), "l"(c));
    return d;
}
__device__ __forceinline__ unsigned long long f32x2_add(
    unsigned long long a, unsigned long long b)
{
    unsigned long long d;
    asm("add.rn.f32x2 %0, %1, %2;" : "=l"(d) : "l"(a), "l"(b));
    return d;
}
__device__ __forceinline__ unsigned long long f32x2_bcast(float x)
{
    unsigned long long d;
    asm("mov.b64 %0, {%1, %1};" : "=l"(d) : "f"(x));
    return d;
}
__device__ __forceinline__ unsigned long long shfl_xor_u64(unsigned long long v, int m)
{
    unsigned int lo = (unsigned int)v, hi = (unsigned int)(v >> 32);
    lo = __shfl_xor_sync(0xffffffffu, lo, m);
    hi = __shfl_xor_sync(0xffffffffu, hi, m);
    return ((unsigned long long)hi << 32) | lo;
}

// ---------------------------------------------------------------------------
// Kernel 1: G01 precompute + fused core2 pack.  NO SMEM.
// grid = (100, 11), block = 128.
//   y < 10 : G01 for i2 = blockIdx.x, i1 in [10y, 10y+10)
//   y == 10: pack core2 for i3 = blockIdx.x
// core0: (1,100,4,16)  elem (i1,n1,r1)    @ i1*64 + n1*16 + r1
// core1: (16,100,4,16) elem (r1,i2,n2,r2) @ r1*6400 + i2*64 + n2*16 + r2
// core2: (16,100,8)    elem (r2,i3,n3)    @ r2*800 + i3*8 + n3
// ---------------------------------------------------------------------------
__global__ void __launch_bounds__(128) tt_precompute(
    const float* __restrict__ core0,
    const float* __restrict__ core1,
    const float* __restrict__ core2)
{
    const int i2 = blockIdx.x;
    const int g  = blockIdx.y;
    const int p  = threadIdx.x;

    if (g == 10) {
        // pack: C2Q[i3*128 + p],  p = j*32 + c*8 + n3,  r2 = 4c + j
        const int i3 = i2;
        const int j  = p >> 5;
        const int c  = (p >> 3) & 3;
        const int n3 = p & 7;
        g_C2Q[i3 * 128 + p] = core2[(4 * c + j) * 800 + i3 * 8 + n3];
#if __CUDA_ARCH__ >= 900
        cudaTriggerProgrammaticLaunchCompletion();
#endif
        return;
    }

    const int n1 = p >> 5;         // constant per warp
    const int rp = (p & 31) * 2;   // rest pair start (n2*16+r2)

    // B column straight from gmem (core1 = 400KB, L2-resident; each LDG.64
    // covers 256B across the warp).  Reused for 10 i1's.
    unsigned long long b2[16];
    #pragma unroll
    for (int r1 = 0; r1 < 16; r1++)
        b2[r1] = *(const unsigned long long*)&core1[r1 * 6400 + i2 * 64 + rp];

    const float* __restrict__ a0 = core0 + (size_t)g * 640 + n1 * 16;

    #pragma unroll
    for (int q = 0; q < 10; q++) {
        // A row fetched 4-wide, warp-uniform (broadcast, L1-hot)
        unsigned long long accE = 0, accO = 0;
        #pragma unroll
        for (int r4 = 0; r4 < 4; r4++) {
            const float4 av = *(const float4*)(a0 + q * 64 + r4 * 4);
            accE = f32x2_fma(f32x2_bcast(av.x), b2[r4 * 4 + 0], accE);
            accO = f32x2_fma(f32x2_bcast(av.y), b2[r4 * 4 + 1], accO);
            accE = f32x2_fma(f32x2_bcast(av.z), b2[r4 * 4 + 2], accE);
            accO = f32x2_fma(f32x2_bcast(av.w), b2[r4 * 4 + 3], accO);
        }
        const unsigned long long acc = f32x2_add(accE, accO);
        const int i1 = g * 10 + q;
        *(unsigned long long*)&g_G01[((size_t)(i1 * 100 + i2)) * 256 + p * 2] = acc;
    }

#if __CUDA_ARCH__ >= 900
    // release: all my G01 stores are before this; pairs with
    // cudaGridDependencySynchronize() in tt_gather.
    cudaTriggerProgrammaticLaunchCompletion();
#endif
}

// ---------------------------------------------------------------------------
// Kernel 2: gather.  1 warp per token, 4 outputs/lane.  (R10/R12 frozen)
// lane L: k = L>>2 (rows k, k+8), c = L&3 (r2-quad [4c,4c+4)),
//         b1 = c&1 (n3-half kept), b2 = c>>1 (n3-pair kept within half).
// PDL: everything up to the grid-dependency sync touches only inputs (x),
// not precompute output.
// ---------------------------------------------------------------------------
__global__ void __launch_bounds__(256, 6) tt_gather(
    const void*  __restrict__ xraw,
    float*       __restrict__ out,
    int n_tok)
{
    const int t    = threadIdx.x;
    const int lane = t & 31;
    const int tok  = blockIdx.x * 8 + (t >> 5);

    // --- prologue (overlaps precompute tail under PDL) ---
    // index dtype autodetect: one 16B broadcast load, 2 samples.
    // int32 data misread as u64 is >= VOC unless the paired hi word is 0
    // (p ~ 1e-12 for both samples); int64 data is always < VOC.
    const ulonglong2 ds = *(const ulonglong2*)xraw;
    const bool is64 = (ds.x < VOC_LL) && (ds.y < VOC_LL);

    long long idxll = 0;
    if (tok < n_tok)
        idxll = is64 ? ((const long long*)xraw)[tok]
                     : (long long)((const int*)xraw)[tok];
    const unsigned int iv  = (unsigned int)idxll;      // < 1e6
    const unsigned int i3  = iv % 100u;
    const unsigned int i12 = iv / 100u;

    const int k  = lane >> 2;
    const int c  = lane & 3;
    const int b1 = c & 1;
    const int b2 = (c >> 1) & 1;

    const float4* __restrict__ Gp = (const float4*)(g_G01 + (size_t)i12 * 256);
    const char* __restrict__ cbase =
        (const char*)g_C2Q + (size_t)i3 * 512 + c * 32;
    const char* cb0 = cbase + 16 * b1;
    const char* cb1 = cbase + 16 * (1 - b1);

#if __CUDA_ARCH__ >= 900
    // acquire: precompute's G01/C2Q stores are visible after this.
    cudaGridDependencySynchronize();
#endif

    if (tok >= n_tok) return;

    // G: 2 contiguous LDG.128 (512B each -> 4 lines per instruction)
    // ga = row k, r2 [4c,4c+4);  gb = row k+8, same quad.
    const float4 ga = Gp[lane];
    const float4 gb = Gp[lane + 32];
    const float gA[4] = { ga.x, ga.y, ga.z, ga.w };
    const float gB[4] = { gb.x, gb.y, gb.z, gb.w };

    // partials: rows {k, k+8}; acc0/acc1 = kept half, acc2/acc3 = send half
    unsigned long long aA0 = 0, aA1 = 0, aA2 = 0, aA3 = 0;
    unsigned long long aB0 = 0, aB1 = 0, aB2 = 0, aB3 = 0;
    #pragma unroll
    for (int j = 0; j < 4; j++) {
        const ulonglong2 cK = *(const ulonglong2*)(cb0 + j * 128);  // kept half
        const ulonglong2 cS = *(const ulonglong2*)(cb1 + j * 128);  // send half
        const unsigned long long ggA = f32x2_bcast(gA[j]);
        const unsigned long long ggB = f32x2_bcast(gB[j]);
        aA0 = f32x2_fma(ggA, cK.x, aA0);
        aA1 = f32x2_fma(ggA, cK.y, aA1);
        aA2 = f32x2_fma(ggA, cS.x, aA2);
        aA3 = f32x2_fma(ggA, cS.y, aA3);
        aB0 = f32x2_fma(ggB, cK.x, aB0);
        aB1 = f32x2_fma(ggB, cK.y, aB1);
        aB2 = f32x2_fma(ggB, cS.x, aB2);
        aB3 = f32x2_fma(ggB, cS.y, aB3);
    }

    // round 1 (xor 1): partner's acc2/acc3 are MY half -> no selects.
    const unsigned long long k0A = f32x2_add(aA0, shfl_xor_u64(aA2, 1));
    const unsigned long long k1A = f32x2_add(aA1, shfl_xor_u64(aA3, 1));
    const unsigned long long k0B = f32x2_add(aB0, shfl_xor_u64(aB2, 1));
    const unsigned long long k1B = f32x2_add(aB1, shfl_xor_u64(aB3, 1));

    // round 2 (xor 2): keep pair 2b1+b2, send the other pair.
    const unsigned long long kkA = b2 ? k1A : k0A;
    const unsigned long long ssA = b2 ? k0A : k1A;
    const unsigned long long kkB = b2 ? k1B : k0B;
    const unsigned long long ssB = b2 ? k0B : k1B;
    unsigned long long fA = f32x2_add(kkA, shfl_xor_u64(ssA, 2));
    unsigned long long fB = f32x2_add(kkB, shfl_xor_u64(ssB, 2));

    if (iv == 0) { fA = 0; fB = 0; }   // PAD row

    // store: rows k and k+8, n3 pair starting at 4b1 + 2b2
    // (warp-wide: 2 stores, each covering a contiguous 256B half-row)
    const int n3off = 4 * b1 + 2 * b2;
    float* obase = out + (size_t)tok * 128;
    *(unsigned long long*)(obase + k * 8 + n3off)       = fA;
    *(unsigned long long*)(obase + (k + 8) * 8 + n3off) = fB;
}

// ---------------------------------------------------------------------------
extern "C" void kernel_launch(void* const* d_in, const int* in_sizes, int n_in,
                              void* d_out, int out_size)
{
    const void*  x     = d_in[0];
    const float* core0 = (const float*)d_in[1];
    const float* core1 = (const float*)d_in[2];
    const float* core2 = (const float*)d_in[3];
    float*       out   = (float*)d_out;

    const int n_tok = in_sizes[0];   // 32768
    const int gblocks = (n_tok + 7) / 8;

    tt_precompute<<<dim3(100, 11), 128>>>(core0, core1, core2);

    // Gather with Programmatic Dependent Launch: overlaps its launch +
    // prologue with the precompute tail.  Fall back to a plain (serial)
    // launch if the attribute path fails for any reason.
    cudaLaunchConfig_t cfg = {};
    cfg.gridDim  = dim3(gblocks, 1, 1);
    cfg.blockDim = dim3(256, 1, 1);
    cfg.dynamicSmemBytes = 0;
    cfg.stream = 0;
    cudaLaunchAttribute attr[1];
    attr[0].id = cudaLaunchAttributeProgrammaticStreamSerialization;
    attr[0].val.programmaticStreamSerializationAllowed = 1;
    cfg.attrs = attr;
    cfg.numAttrs = 1;

    cudaError_t e = cudaLaunchKernelEx(&cfg, tt_gather, x, out, n_tok);
    if (e != cudaSuccess) {
        (void)cudaGetLastError();   // clear sticky error state
        tt_gather<<<gblocks, 256>>>(x, out, n_tok);
    }
}

// round 15
// speedup vs baseline: 1.0150x; 1.0150x over previous
#include <cuda_runtime.h>
#include <cstdint>

// ---------------------------------------------------------------------------
// TT embedding:  VOC = 100^3,  EMB = 4*4*8 = 128,  RANK = 16
//   out[tok, n1*32+n2*8+n3] = sum_{r1,r2} core0[i1,n1,r1]*core1[r1,i2,n2,r2]*core2[r2,i3,n3]
// idx = i1*10000 + i2*100 + i3; idx==0 (PAD) -> zero row.
//
// Kernel 1 : G01[i12][row*16+r2] = sum_r1 core0*core1  (10.2MB, L2-resident)
//            + fused pack of core2 into C2Q (51KB), r2 = 4c+j.  No smem.
// Kernel 2 : warp handles TWO tokens, SOFTWARE-PIPELINED (not interleaved):
//            tok1's idx + G row are prefetched before tok0's compute, hiding
//            tok1's L2 latency under tok0's FMA/reduce/store.  Per-token body
//            is the R10/R12-frozen minimal-wavefront layout:
//   G: 2x contiguous LDG.128 (8 wf).  C: 8 instr, one 128B line each (8 wf),
//   address-permuted so reduce round 1 needs no selects.  2-round
//   reduce-scatter, 2x contiguous STG.64.
// ---------------------------------------------------------------------------

#define VOC_LL 1000000ULL

__device__ float g_G01[10000 * 256];
__device__ float g_C2Q[100 * 128];   // [i3][j][c][n3] = core2[4c+j][i3][n3]

// ---- packed fp32x2 helpers (sm_103a) --------------------------------------
__device__ __forceinline__ unsigned long long f32x2_fma(
    unsigned long long a, unsigned long long b, unsigned long long c)
{
    unsigned long long d;
    asm("fma.rn.f32x2 %0, %1, %2, %3;" : "=l"(d) : "l"(a), "l"(b), "l"(c));
    return d;
}
__device__ __forceinline__ unsigned long long f32x2_add(
    unsigned long long a, unsigned long long b)
{
    unsigned long long d;
    asm("add.rn.f32x2 %0, %1, %2;" : "=l"(d) : "l"(a), "l"(b));
    return d;
}
__device__ __forceinline__ unsigned long long f32x2_bcast(float x)
{
    unsigned long long d;
    asm("mov.b64 %0, {%1, %1};" : "=l"(d) : "f"(x));
    return d;
}
__device__ __forceinline__ unsigned long long shfl_xor_u64(unsigned long long v, int m)
{
    unsigned int lo = (unsigned int)v, hi = (unsigned int)(v >> 32);
    lo = __shfl_xor_sync(0xffffffffu, lo, m);
    hi = __shfl_xor_sync(0xffffffffu, hi, m);
    return ((unsigned long long)hi << 32) | lo;
}

// ---------------------------------------------------------------------------
// Kernel 1: G01 precompute + fused core2 pack.  NO SMEM.  (R13 frozen)
// grid = (100, 11), block = 128.
//   y < 10 : G01 for i2 = blockIdx.x, i1 in [10y, 10y+10)
//   y == 10: pack core2 for i3 = blockIdx.x
// core0: (1,100,4,16)  elem (i1,n1,r1)    @ i1*64 + n1*16 + r1
// core1: (16,100,4,16) elem (r1,i2,n2,r2) @ r1*6400 + i2*64 + n2*16 + r2
// core2: (16,100,8)    elem (r2,i3,n3)    @ r2*800 + i3*8 + n3
// ---------------------------------------------------------------------------
__global__ void __launch_bounds__(128) tt_precompute(
    const float* __restrict__ core0,
    const float* __restrict__ core1,
    const float* __restrict__ core2)
{
    const int i2 = blockIdx.x;
    const int g  = blockIdx.y;
    const int p  = threadIdx.x;

    if (g == 10) {
        // pack: C2Q[i3*128 + p],  p = j*32 + c*8 + n3,  r2 = 4c + j
        const int i3 = i2;
        const int j  = p >> 5;
        const int c  = (p >> 3) & 3;
        const int n3 = p & 7;
        g_C2Q[i3 * 128 + p] = core2[(4 * c + j) * 800 + i3 * 8 + n3];
        return;
    }

    const int n1 = p >> 5;         // constant per warp
    const int rp = (p & 31) * 2;   // rest pair start (n2*16+r2)

    // B column straight from gmem (core1 = 400KB, L2-resident), reused 10x.
    unsigned long long b2[16];
    #pragma unroll
    for (int r1 = 0; r1 < 16; r1++)
        b2[r1] = *(const unsigned long long*)&core1[r1 * 6400 + i2 * 64 + rp];

    const float* __restrict__ a0 = core0 + (size_t)g * 640 + n1 * 16;

    #pragma unroll
    for (int q = 0; q < 10; q++) {
        unsigned long long accE = 0, accO = 0;
        #pragma unroll
        for (int r4 = 0; r4 < 4; r4++) {
            const float4 av = *(const float4*)(a0 + q * 64 + r4 * 4);
            accE = f32x2_fma(f32x2_bcast(av.x), b2[r4 * 4 + 0], accE);
            accO = f32x2_fma(f32x2_bcast(av.y), b2[r4 * 4 + 1], accO);
            accE = f32x2_fma(f32x2_bcast(av.z), b2[r4 * 4 + 2], accE);
            accO = f32x2_fma(f32x2_bcast(av.w), b2[r4 * 4 + 3], accO);
        }
        const unsigned long long acc = f32x2_add(accE, accO);
        const int i1 = g * 10 + q;
        *(unsigned long long*)&g_G01[((size_t)(i1 * 100 + i2)) * 256 + p * 2] = acc;
    }
}

// ---------------------------------------------------------------------------
// Per-token gather body (R10/R12-frozen math).  ga/gb already loaded.
// ---------------------------------------------------------------------------
__device__ __forceinline__ void gather_body(
    const float4 ga, const float4 gb,
    const char* cb0, const char* cb1,
    unsigned int iv, int k, int b2v, int n3off,
    float* __restrict__ obase)
{
    const float gA[4] = { ga.x, ga.y, ga.z, ga.w };
    const float gB[4] = { gb.x, gb.y, gb.z, gb.w };

    unsigned long long aA0 = 0, aA1 = 0, aA2 = 0, aA3 = 0;
    unsigned long long aB0 = 0, aB1 = 0, aB2 = 0, aB3 = 0;
    #pragma unroll
    for (int j = 0; j < 4; j++) {
        const ulonglong2 cK = *(const ulonglong2*)(cb0 + j * 128);  // kept half
        const ulonglong2 cS = *(const ulonglong2*)(cb1 + j * 128);  // send half
        const unsigned long long ggA = f32x2_bcast(gA[j]);
        const unsigned long long ggB = f32x2_bcast(gB[j]);
        aA0 = f32x2_fma(ggA, cK.x, aA0);
        aA1 = f32x2_fma(ggA, cK.y, aA1);
        aA2 = f32x2_fma(ggA, cS.x, aA2);
        aA3 = f32x2_fma(ggA, cS.y, aA3);
        aB0 = f32x2_fma(ggB, cK.x, aB0);
        aB1 = f32x2_fma(ggB, cK.y, aB1);
        aB2 = f32x2_fma(ggB, cS.x, aB2);
        aB3 = f32x2_fma(ggB, cS.y, aB3);
    }

    // round 1 (xor 1): partner's acc2/acc3 are MY half -> no selects.
    const unsigned long long k0A = f32x2_add(aA0, shfl_xor_u64(aA2, 1));
    const unsigned long long k1A = f32x2_add(aA1, shfl_xor_u64(aA3, 1));
    const unsigned long long k0B = f32x2_add(aB0, shfl_xor_u64(aB2, 1));
    const unsigned long long k1B = f32x2_add(aB1, shfl_xor_u64(aB3, 1));

    // round 2 (xor 2): keep pair 2b1+b2, send the other pair.
    const unsigned long long kkA = b2v ? k1A : k0A;
    const unsigned long long ssA = b2v ? k0A : k1A;
    const unsigned long long kkB = b2v ? k1B : k0B;
    const unsigned long long ssB = b2v ? k0B : k1B;
    unsigned long long fA = f32x2_add(kkA, shfl_xor_u64(ssA, 2));
    unsigned long long fB = f32x2_add(kkB, shfl_xor_u64(ssB, 2));

    if (iv == 0) { fA = 0; fB = 0; }   // PAD row

    *(unsigned long long*)(obase + k * 8 + n3off)       = fA;
    *(unsigned long long*)(obase + (k + 8) * 8 + n3off) = fB;
}

// ---------------------------------------------------------------------------
// Kernel 2: gather.  1 warp = 2 tokens, software-pipelined.
// lane L: k = L>>2 (rows k, k+8), c = L&3 (r2-quad [4c,4c+4)),
//         b1 = c&1 (n3-half kept), b2 = c>>1 (n3-pair kept within half).
// tok1 = tok0 + n_tok/2 keeps both store streams bulk-coalesced.
// ---------------------------------------------------------------------------
__global__ void __launch_bounds__(256, 4) tt_gather(
    const void*  __restrict__ xraw,
    float*       __restrict__ out,
    int n_tok)
{
    const int t    = threadIdx.x;
    const int lane = t & 31;
    const int half = (n_tok + 1) >> 1;
    const int tok0 = blockIdx.x * 8 + (t >> 5);
    if (tok0 >= half) return;
    const int tok1  = tok0 + half;
    const bool have1 = (tok1 < n_tok);

    // --- index dtype autodetect: one 16B broadcast load, 2 samples. ---
    const ulonglong2 ds = *(const ulonglong2*)xraw;
    const bool is64 = (ds.x < VOC_LL) && (ds.y < VOC_LL);

    const long long idx0 = is64 ? ((const long long*)xraw)[tok0]
                                : (long long)((const int*)xraw)[tok0];
    const long long idx1 = have1
        ? (is64 ? ((const long long*)xraw)[tok1]
                : (long long)((const int*)xraw)[tok1])
        : 0;
    const unsigned int iv0  = (unsigned int)idx0;
    const unsigned int iv1  = (unsigned int)idx1;
    const unsigned int i3_0 = iv0 % 100u, i12_0 = iv0 / 100u;
    const unsigned int i3_1 = iv1 % 100u, i12_1 = iv1 / 100u;

    const int k   = lane >> 2;
    const int c   = lane & 3;
    const int b1  = c & 1;
    const int b2v = (c >> 1) & 1;
    const int n3off = 4 * b1 + 2 * b2v;

    // --- prefetch BOTH tokens' G rows up front (long-latency L2 loads) ---
    const float4* __restrict__ Gp0 = (const float4*)(g_G01 + (size_t)i12_0 * 256);
    const float4* __restrict__ Gp1 = (const float4*)(g_G01 + (size_t)i12_1 * 256);
    const float4 ga0 = Gp0[lane];
    const float4 gb0 = Gp0[lane + 32];
    const float4 ga1 = Gp1[lane];        // lands while tok0 computes
    const float4 gb1 = Gp1[lane + 32];

    // C2P pointers (L1-hot 51KB table), address-permuted per lane
    const char* base0 = (const char*)g_C2Q + (size_t)i3_0 * 512 + c * 32;
    const char* base1 = (const char*)g_C2Q + (size_t)i3_1 * 512 + c * 32;
    const char* cb0_0 = base0 + 16 * b1;
    const char* cb1_0 = base0 + 16 * (1 - b1);
    const char* cb0_1 = base1 + 16 * b1;
    const char* cb1_1 = base1 + 16 * (1 - b1);

    // --- token 0: compute + reduce + store ---
    gather_body(ga0, gb0, cb0_0, cb1_0, iv0, k, b2v, n3off,
                out + (size_t)tok0 * 128);

    // --- token 1 (G already in registers) ---
    if (have1)
        gather_body(ga1, gb1, cb0_1, cb1_1, iv1, k, b2v, n3off,
                    out + (size_t)tok1 * 128);
}

// ---------------------------------------------------------------------------
extern "C" void kernel_launch(void* const* d_in, const int* in_sizes, int n_in,
                              void* d_out, int out_size)
{
    const void*  x     = d_in[0];
    const float* core0 = (const float*)d_in[1];
    const float* core1 = (const float*)d_in[2];
    const float* core2 = (const float*)d_in[3];
    float*       out   = (float*)d_out;

    const int n_tok = in_sizes[0];   // 32768
    const int half  = (n_tok + 1) >> 1;

    tt_precompute<<<dim3(100, 11), 128>>>(core0, core1, core2);
    tt_gather<<<(half + 7) / 8, 256>>>(x, out, n_tok);
}

// round 16
// speedup vs baseline: 1.0288x; 1.0135x over previous
#include <cuda_runtime.h>
#include <cstdint>

// ---------------------------------------------------------------------------
// TT embedding:  VOC = 100^3,  EMB = 4*4*8 = 128,  RANK = 16
//   out[tok, n1*32+n2*8+n3] = sum_{r1,r2} core0[i1,n1,r1]*core1[r1,i2,n2,r2]*core2[r2,i3,n3]
// idx = i1*10000 + i2*100 + i3; idx==0 (PAD) -> zero row.
//
// Kernel 1 : G01[i12][row*16+r2] = sum_r1 core0*core1  (10.2MB, L2-resident)
//            + fused pack of core2 into C2Q (51KB), r2 = 4c+j.  No smem.
// Kernel 2 : warp handles FOUR tokens, rolling depth-2 software pipeline:
//            G rows of tokens m and m+1 are in flight while token m-1
//            computes.  Per-token body is the R10/R12-frozen layout:
//   G: 2x contiguous LDG.128 (8 wf).  C: 8 instr, one 128B line each (8 wf),
//   address-permuted so reduce round 1 needs no selects.  2-round
//   reduce-scatter, 2x contiguous STG.64.
// ---------------------------------------------------------------------------

#define VOC_LL 1000000ULL

__device__ float g_G01[10000 * 256];
__device__ float g_C2Q[100 * 128];   // [i3][j][c][n3] = core2[4c+j][i3][n3]

// ---- packed fp32x2 helpers (sm_103a) --------------------------------------
__device__ __forceinline__ unsigned long long f32x2_fma(
    unsigned long long a, unsigned long long b, unsigned long long c)
{
    unsigned long long d;
    asm("fma.rn.f32x2 %0, %1, %2, %3;" : "=l"(d) : "l"(a), "l"(b), "l"(c));
    return d;
}
__device__ __forceinline__ unsigned long long f32x2_add(
    unsigned long long a, unsigned long long b)
{
    unsigned long long d;
    asm("add.rn.f32x2 %0, %1, %2;" : "=l"(d) : "l"(a), "l"(b));
    return d;
}
__device__ __forceinline__ unsigned long long f32x2_bcast(float x)
{
    unsigned long long d;
    asm("mov.b64 %0, {%1, %1};" : "=l"(d) : "f"(x));
    return d;
}
__device__ __forceinline__ unsigned long long shfl_xor_u64(unsigned long long v, int m)
{
    unsigned int lo = (unsigned int)v, hi = (unsigned int)(v >> 32);
    lo = __shfl_xor_sync(0xffffffffu, lo, m);
    hi = __shfl_xor_sync(0xffffffffu, hi, m);
    return ((unsigned long long)hi << 32) | lo;
}

// ---------------------------------------------------------------------------
// Kernel 1: G01 precompute + fused core2 pack.  NO SMEM.  (R13 frozen)
// grid = (100, 11), block = 128.
//   y < 10 : G01 for i2 = blockIdx.x, i1 in [10y, 10y+10)
//   y == 10: pack core2 for i3 = blockIdx.x
// core0: (1,100,4,16)  elem (i1,n1,r1)    @ i1*64 + n1*16 + r1
// core1: (16,100,4,16) elem (r1,i2,n2,r2) @ r1*6400 + i2*64 + n2*16 + r2
// core2: (16,100,8)    elem (r2,i3,n3)    @ r2*800 + i3*8 + n3
// ---------------------------------------------------------------------------
__global__ void __launch_bounds__(128) tt_precompute(
    const float* __restrict__ core0,
    const float* __restrict__ core1,
    const float* __restrict__ core2)
{
    const int i2 = blockIdx.x;
    const int g  = blockIdx.y;
    const int p  = threadIdx.x;

    if (g == 10) {
        // pack: C2Q[i3*128 + p],  p = j*32 + c*8 + n3,  r2 = 4c + j
        const int i3 = i2;
        const int j  = p >> 5;
        const int c  = (p >> 3) & 3;
        const int n3 = p & 7;
        g_C2Q[i3 * 128 + p] = core2[(4 * c + j) * 800 + i3 * 8 + n3];
        return;
    }

    const int n1 = p >> 5;         // constant per warp
    const int rp = (p & 31) * 2;   // rest pair start (n2*16+r2)

    // B column straight from gmem (core1 = 400KB, L2-resident), reused 10x.
    unsigned long long b2[16];
    #pragma unroll
    for (int r1 = 0; r1 < 16; r1++)
        b2[r1] = *(const unsigned long long*)&core1[r1 * 6400 + i2 * 64 + rp];

    const float* __restrict__ a0 = core0 + (size_t)g * 640 + n1 * 16;

    #pragma unroll
    for (int q = 0; q < 10; q++) {
        unsigned long long accE = 0, accO = 0;
        #pragma unroll
        for (int r4 = 0; r4 < 4; r4++) {
            const float4 av = *(const float4*)(a0 + q * 64 + r4 * 4);
            accE = f32x2_fma(f32x2_bcast(av.x), b2[r4 * 4 + 0], accE);
            accO = f32x2_fma(f32x2_bcast(av.y), b2[r4 * 4 + 1], accO);
            accE = f32x2_fma(f32x2_bcast(av.z), b2[r4 * 4 + 2], accE);
            accO = f32x2_fma(f32x2_bcast(av.w), b2[r4 * 4 + 3], accO);
        }
        const unsigned long long acc = f32x2_add(accE, accO);
        const int i1 = g * 10 + q;
        *(unsigned long long*)&g_G01[((size_t)(i1 * 100 + i2)) * 256 + p * 2] = acc;
    }
}

// ---------------------------------------------------------------------------
// Per-token gather body (R10/R12-frozen math).  ga/gb already loaded;
// C2Q base pointers recomputed from i3 (ALU, keeps register count flat).
// ---------------------------------------------------------------------------
__device__ __forceinline__ void gather_body(
    const float4 ga, const float4 gb,
    unsigned int i3, unsigned int iv,
    int c, int b1, int k, int b2v, int n3off,
    float* __restrict__ obase)
{
    const char* base = (const char*)g_C2Q + (size_t)i3 * 512 + c * 32;
    const char* cb0  = base + 16 * b1;        // n3-half this lane KEEPS
    const char* cb1  = base + 16 * (1 - b1);  // half it will send

    const float gA[4] = { ga.x, ga.y, ga.z, ga.w };
    const float gB[4] = { gb.x, gb.y, gb.z, gb.w };

    unsigned long long aA0 = 0, aA1 = 0, aA2 = 0, aA3 = 0;
    unsigned long long aB0 = 0, aB1 = 0, aB2 = 0, aB3 = 0;
    #pragma unroll
    for (int j = 0; j < 4; j++) {
        const ulonglong2 cK = *(const ulonglong2*)(cb0 + j * 128);  // kept half
        const ulonglong2 cS = *(const ulonglong2*)(cb1 + j * 128);  // send half
        const unsigned long long ggA = f32x2_bcast(gA[j]);
        const unsigned long long ggB = f32x2_bcast(gB[j]);
        aA0 = f32x2_fma(ggA, cK.x, aA0);
        aA1 = f32x2_fma(ggA, cK.y, aA1);
        aA2 = f32x2_fma(ggA, cS.x, aA2);
        aA3 = f32x2_fma(ggA, cS.y, aA3);
        aB0 = f32x2_fma(ggB, cK.x, aB0);
        aB1 = f32x2_fma(ggB, cK.y, aB1);
        aB2 = f32x2_fma(ggB, cS.x, aB2);
        aB3 = f32x2_fma(ggB, cS.y, aB3);
    }

    // round 1 (xor 1): partner's acc2/acc3 are MY half -> no selects.
    const unsigned long long k0A = f32x2_add(aA0, shfl_xor_u64(aA2, 1));
    const unsigned long long k1A = f32x2_add(aA1, shfl_xor_u64(aA3, 1));
    const unsigned long long k0B = f32x2_add(aB0, shfl_xor_u64(aB2, 1));
    const unsigned long long k1B = f32x2_add(aB1, shfl_xor_u64(aB3, 1));

    // round 2 (xor 2): keep pair 2b1+b2, send the other pair.
    const unsigned long long kkA = b2v ? k1A : k0A;
    const unsigned long long ssA = b2v ? k0A : k1A;
    const unsigned long long kkB = b2v ? k1B : k0B;
    const unsigned long long ssB = b2v ? k0B : k1B;
    unsigned long long fA = f32x2_add(kkA, shfl_xor_u64(ssA, 2));
    unsigned long long fB = f32x2_add(kkB, shfl_xor_u64(ssB, 2));

    if (iv == 0) { fA = 0; fB = 0; }   // PAD row

    *(unsigned long long*)(obase + k * 8 + n3off)       = fA;
    *(unsigned long long*)(obase + (k + 8) * 8 + n3off) = fB;
}

// ---------------------------------------------------------------------------
// Kernel 2: gather.  1 warp = 4 tokens, rolling depth-2 pipeline.
// lane L: k = L>>2 (rows k, k+8), c = L&3 (r2-quad [4c,4c+4)),
//         b1 = c&1 (n3-half kept), b2 = c>>1 (n3-pair kept within half).
// tokens m = tok0 + m*quarter keep all four store streams bulk-coalesced.
// ---------------------------------------------------------------------------
__global__ void __launch_bounds__(256, 4) tt_gather(
    const void*  __restrict__ xraw,
    float*       __restrict__ out,
    int n_tok)
{
    const int t       = threadIdx.x;
    const int lane    = t & 31;
    const int quarter = (n_tok + 3) >> 2;
    const int tok0    = blockIdx.x * 8 + (t >> 5);
    if (tok0 >= quarter) return;

    // --- index dtype autodetect: one 16B broadcast load, 2 samples. ---
    const ulonglong2 ds = *(const ulonglong2*)xraw;
    const bool is64 = (ds.x < VOC_LL) && (ds.y < VOC_LL);

    unsigned int iv[4], i3[4], i12[4];
    int tk[4];
    bool have[4];
    #pragma unroll
    for (int m = 0; m < 4; m++) {
        tk[m]   = tok0 + m * quarter;
        have[m] = (tk[m] < n_tok);
        long long idx = 0;
        if (have[m])
            idx = is64 ? ((const long long*)xraw)[tk[m]]
                       : (long long)((const int*)xraw)[tk[m]];
        iv[m]  = (unsigned int)idx;       // < 1e6
        i3[m]  = iv[m] % 100u;
        i12[m] = iv[m] / 100u;
    }

    const int k   = lane >> 2;
    const int c   = lane & 3;
    const int b1  = c & 1;
    const int b2v = (c >> 1) & 1;
    const int n3off = 4 * b1 + 2 * b2v;

    // --- rolling pipeline: G(m), G(m+1) in flight while body(m-1) runs ---
    const float4* __restrict__ G0 = (const float4*)(g_G01 + (size_t)i12[0] * 256);
    const float4* __restrict__ G1 = (const float4*)(g_G01 + (size_t)i12[1] * 256);
    float4 ga0 = G0[lane], gb0 = G0[lane + 32];
    float4 ga1 = G1[lane], gb1 = G1[lane + 32];

    gather_body(ga0, gb0, i3[0], iv[0], c, b1, k, b2v, n3off,
                out + (size_t)tk[0] * 128);

    const float4* __restrict__ G2 = (const float4*)(g_G01 + (size_t)i12[2] * 256);
    float4 ga2 = G2[lane], gb2 = G2[lane + 32];

    if (have[1])
        gather_body(ga1, gb1, i3[1], iv[1], c, b1, k, b2v, n3off,
                    out + (size_t)tk[1] * 128);

    const float4* __restrict__ G3 = (const float4*)(g_G01 + (size_t)i12[3] * 256);
    float4 ga3 = G3[lane], gb3 = G3[lane + 32];

    if (have[2])
        gather_body(ga2, gb2, i3[2], iv[2], c, b1, k, b2v, n3off,
                    out + (size_t)tk[2] * 128);

    if (have[3])
        gather_body(ga3, gb3, i3[3], iv[3], c, b1, k, b2v, n3off,
                    out + (size_t)tk[3] * 128);
}

// ---------------------------------------------------------------------------
extern "C" void kernel_launch(void* const* d_in, const int* in_sizes, int n_in,
                              void* d_out, int out_size)
{
    const void*  x     = d_in[0];
    const float* core0 = (const float*)d_in[1];
    const float* core1 = (const float*)d_in[2];
    const float* core2 = (const float*)d_in[3];
    float*       out   = (float*)d_out;

    const int n_tok   = in_sizes[0];   // 32768
    const int quarter = (n_tok + 3) >> 2;

    tt_precompute<<<dim3(100, 11), 128>>>(core0, core1, core2);
    tt_gather<<<(quarter + 7) / 8, 256>>>(x, out, n_tok);
}